// round 3
// baseline (speedup 1.0000x reference)
#include <cuda_runtime.h>
#include <math.h>
#include <cstdint>

#define NN 8192
#define FF 256
#define DD 64
#define KH 2

// ---------------- scratch (static device globals; no allocation) -------------
__device__ float g_HW [KH*NN*DD];   // [k][n][d]
__device__ float g_e1 [KH*NN];
__device__ float g_e2 [KH*NN];
__device__ float g_p1 [KH*NN];      // exp(e1)
__device__ float g_p51[KH*NN];      // exp(0.2 e1)
__device__ float g_p2 [KH*NN];      // exp(e2)
__device__ float g_p52[KH*NN];      // exp(0.2 e2)
__device__ float g_q1 [KH*NN];      // p1 / Z
__device__ float g_q5 [KH*NN];      // p51 / Z
__device__ unsigned g_mask[NN*(NN/32)];  // bitpacked A, row-major [j][i/32]

// ---------------- small PTX helpers (all plain sm_80+ PTX) ------------------
__device__ __forceinline__ unsigned f2tf32(float f) {
    unsigned r;
    asm("cvt.rna.tf32.f32 %0, %1;" : "=r"(r) : "f"(f));
    return r;
}
__device__ __forceinline__ void mma_tf32(float* d, const unsigned* a, const unsigned* bf) {
    asm volatile(
        "mma.sync.aligned.m16n8k8.row.col.f32.tf32.tf32.f32 "
        "{%0,%1,%2,%3}, {%4,%5,%6,%7}, {%8,%9}, {%0,%1,%2,%3};"
        : "+f"(d[0]), "+f"(d[1]), "+f"(d[2]), "+f"(d[3])
        : "r"(a[0]), "r"(a[1]), "r"(a[2]), "r"(a[3]), "r"(bf[0]), "r"(bf[1]));
}

// ---------------- kernel 1: HW[k][n][d] = sum_f H[n][f] W[k][f][d] ----------
__global__ void k_hw(const float* __restrict__ H, const float* __restrict__ W) {
    __shared__ float Ws[64][128];
    __shared__ float Hs[32][64];
    const int tid = threadIdx.x;
    const int tx = tid & 31;
    const int ty = tid >> 5;
    const int n0 = blockIdx.x * 32;

    float acc[4][4];
#pragma unroll
    for (int a = 0; a < 4; a++)
#pragma unroll
        for (int b = 0; b < 4; b++) acc[a][b] = 0.f;

    for (int fc = 0; fc < FF; fc += 64) {
#pragma unroll
        for (int q = 0; q < 8; q++) {
            int idx = q * 256 + tid;
            int kk = idx >> 5, c4 = idx & 31;
            int c = c4 * 4;
            int k = c >> 6, d = c & 63;
            float4 v = *(const float4*)(W + k * (FF * DD) + (fc + kk) * DD + d);
            *(float4*)(&Ws[kk][c]) = v;
        }
#pragma unroll
        for (int q = 0; q < 2; q++) {
            int idx = q * 256 + tid;
            int r = idx >> 4, k4 = idx & 15;
            float4 v = *(const float4*)(H + (n0 + r) * FF + fc + k4 * 4);
            *(float4*)(&Hs[r][k4 * 4]) = v;
        }
        __syncthreads();
#pragma unroll 8
        for (int kk = 0; kk < 64; kk++) {
            float4 bv = *(const float4*)(&Ws[kk][tx * 4]);
            float a0 = Hs[ty * 4 + 0][kk];
            float a1 = Hs[ty * 4 + 1][kk];
            float a2 = Hs[ty * 4 + 2][kk];
            float a3 = Hs[ty * 4 + 3][kk];
            acc[0][0] += a0 * bv.x; acc[0][1] += a0 * bv.y; acc[0][2] += a0 * bv.z; acc[0][3] += a0 * bv.w;
            acc[1][0] += a1 * bv.x; acc[1][1] += a1 * bv.y; acc[1][2] += a1 * bv.z; acc[1][3] += a1 * bv.w;
            acc[2][0] += a2 * bv.x; acc[2][1] += a2 * bv.y; acc[2][2] += a2 * bv.z; acc[2][3] += a2 * bv.w;
            acc[3][0] += a3 * bv.x; acc[3][1] += a3 * bv.y; acc[3][2] += a3 * bv.z; acc[3][3] += a3 * bv.w;
        }
        __syncthreads();
    }
    const int c = tx * 4;
    const int k = c >> 6, d = c & 63;
#pragma unroll
    for (int s = 0; s < 4; s++) {
        int n = n0 + ty * 4 + s;
        float4 o = make_float4(acc[s][0], acc[s][1], acc[s][2], acc[s][3]);
        *(float4*)(g_HW + (k * NN + n) * DD + d) = o;
    }
}

// ------- kernel 2: e1/e2 per (k,n) + exp tables --------------------------
__global__ void k_e(const float* __restrict__ a1, const float* __restrict__ a2) {
    __shared__ float a1s[128], a2s[128];
    const int tid = threadIdx.x;
    if (tid < 128) a1s[tid] = a1[tid];
    else           a2s[tid - 128] = a2[tid - 128];
    __syncthreads();
    const int t = blockIdx.x * 256 + tid;
    const int k = t >> 13;
    const float* hw = g_HW + (size_t)t * DD;
    const float* A1 = a1s + k * 64;
    const float* A2 = a2s + k * 64;
    float e1 = 0.f, e2 = 0.f;
#pragma unroll
    for (int d4 = 0; d4 < 16; d4++) {
        float4 h = *(const float4*)(hw + d4 * 4);
        e1 += h.x * A1[d4 * 4 + 0] + h.y * A1[d4 * 4 + 1] + h.z * A1[d4 * 4 + 2] + h.w * A1[d4 * 4 + 3];
        e2 += h.x * A2[d4 * 4 + 0] + h.y * A2[d4 * 4 + 1] + h.z * A2[d4 * 4 + 2] + h.w * A2[d4 * 4 + 3];
    }
    g_e1[t] = e1;             g_e2[t] = e2;
    g_p1[t] = expf(e1);       g_p51[t] = expf(0.2f * e1);
    g_p2[t] = expf(e2);       g_p52[t] = expf(0.2f * e2);
}

// ------- kernel 3: softmax denominators Z + bitpack A --------------------
__global__ void k_z(const int* __restrict__ A) {
    __shared__ float e2s[2][256], p2s[2][256], p52s[2][256];
    __shared__ float red[32][8];
    const int tid = threadIdx.x;
    const int lane = tid & 31, wrp = tid >> 5;
    const int j0 = blockIdx.x * 8;

    float e1r[8][2];
#pragma unroll
    for (int j = 0; j < 8; j++) {
        e1r[j][0] = g_e1[j0 + j];
        e1r[j][1] = g_e1[NN + j0 + j];
    }
    float sums[8][2][2];
#pragma unroll
    for (int j = 0; j < 8; j++)
#pragma unroll
        for (int k = 0; k < 2; k++) { sums[j][k][0] = 0.f; sums[j][k][1] = 0.f; }

    for (int ci = 0; ci < 32; ci++) {
#pragma unroll
        for (int q = 0; q < 6; q++) {
            int idx = q * 256 + tid;
            int arr = idx / 512, k = (idx >> 8) & 1, el = idx & 255;
            int gi = k * NN + ci * 256 + el;
            if (arr == 0)      e2s [k][el] = g_e2 [gi];
            else if (arr == 1) p2s [k][el] = g_p2 [gi];
            else               p52s[k][el] = g_p52[gi];
        }
        __syncthreads();
        const float e2v0 = e2s[0][tid],  e2v1 = e2s[1][tid];
        const float p2v0 = p2s[0][tid],  p2v1 = p2s[1][tid];
        const float p52v0 = p52s[0][tid], p52v1 = p52s[1][tid];
        const int ibase = ci * 256;
#pragma unroll
        for (int j = 0; j < 8; j++) {
            int a = A[(j0 + j) * NN + ibase + tid];
            unsigned bal = __ballot_sync(0xffffffffu, a != 0);
            if (lane == 0) g_mask[(j0 + j) * (NN / 32) + ci * 8 + wrp] = bal;
            float am = (a != 0) ? 1.0f : 0.0f;
            {
                float s = e1r[j][0] + e2v0;
                bool pos = s >= 0.f;
                sums[j][0][0] += am * (pos ? p2v0 : 0.f);
                sums[j][0][1] += am * (pos ? 0.f : p52v0);
            }
            {
                float s = e1r[j][1] + e2v1;
                bool pos = s >= 0.f;
                sums[j][1][0] += am * (pos ? p2v1 : 0.f);
                sums[j][1][1] += am * (pos ? 0.f : p52v1);
            }
        }
        __syncthreads();
    }
#pragma unroll
    for (int v = 0; v < 32; v++) {
        int j = v >> 2, k = (v >> 1) & 1, tp = v & 1;
        float val = sums[j][k][tp];
        val += __shfl_down_sync(0xffffffffu, val, 16);
        val += __shfl_down_sync(0xffffffffu, val, 8);
        val += __shfl_down_sync(0xffffffffu, val, 4);
        val += __shfl_down_sync(0xffffffffu, val, 2);
        val += __shfl_down_sync(0xffffffffu, val, 1);
        if (lane == 0) red[v][wrp] = val;
    }
    __syncthreads();
    if (tid < 16) {
        int j = tid >> 1, k = tid & 1;
        float s0 = 0.f, s5 = 0.f;
#pragma unroll
        for (int w = 0; w < 8; w++) {
            s0 += red[(j * 2 + k) * 2 + 0][w];
            s5 += red[(j * 2 + k) * 2 + 1][w];
        }
        int gi = k * NN + j0 + j;
        float p1 = g_p1[gi], p51 = g_p51[gi];
        float rZ = 1.0f / (p1 * s0 + p51 * s5);
        g_q1[gi] = p1 * rZ;
        g_q5[gi] = p51 * rZ;
    }
}

// ------- kernel 4 (mma.sync tf32): out[k,i,:] = sum_j attn[k,j,i]*HW[k,j,:] -
// CTA: 256 thr / 8 warps, tile M=128 (i) x N=64 (d), head = blockIdx.y.
// Warp w: m32 block mi=w&3, n32 block nh=w>>2. K loop over 256 j-tiles of 32.
// A fragments (attn) are computed straight into registers from j-tables;
// B = HW^T tile staged in smem with stride 36 (conflict-free frag reads).
__global__ void __launch_bounds__(256) k_out_mma(const float* __restrict__ bias,
                                                 float* __restrict__ out) {
    __shared__ unsigned Bs[2][64][36];   // tf32 bits, [d][j] stride 36
    __shared__ float4   jtab[2][32];     // {e1, q1, q5, -} per j
    __shared__ unsigned maskt[2][128];   // [j][word 0..3] for this i-tile
    __shared__ float e2t[128], p2t[128], p52t[128];

    const int tid  = threadIdx.x;
    const int wid  = tid >> 5;
    const int lane = tid & 31;
    const int kh   = blockIdx.y;
    const int i0   = blockIdx.x * 128;
    const int kbase = kh * NN;
    const int mrow0 = i0 >> 5;

    const int mi = wid & 3;              // m32 block
    const int nh = wid >> 2;             // n32 block
    const int rr = lane >> 2;            // 0..7
    const int cc = lane & 3;             // 0..3

    if (tid < 128) {
        e2t [tid] = g_e2 [kbase + i0 + tid];
        p2t [tid] = g_p2 [kbase + i0 + tid];
        p52t[tid] = g_p52[kbase + i0 + tid];
    }

#define LOAD_TILE(JT, BUF) do {                                                   \
    const int j0_ = (JT) * 32;                                                    \
    if (tid < 32) {                                                               \
        jtab[BUF][tid] = make_float4(g_e1[kbase + j0_ + tid],                     \
                                     g_q1[kbase + j0_ + tid],                     \
                                     g_q5[kbase + j0_ + tid], 0.f);               \
    } else if (tid < 160) {                                                       \
        int t2 = tid - 32;                                                        \
        maskt[BUF][t2] = g_mask[(j0_ + (t2 >> 2)) * (NN / 32) + mrow0 + (t2 & 3)];\
    }                                                                             \
    {                                                                             \
        int bj = tid & 31, bd0 = (tid >> 5) * 8;                                  \
        const float* src = g_HW + (size_t)(kbase + j0_ + bj) * DD + bd0;          \
        float4 v0 = *(const float4*)(src);                                        \
        float4 v1 = *(const float4*)(src + 4);                                    \
        Bs[BUF][bd0 + 0][bj] = f2tf32(v0.x);                                      \
        Bs[BUF][bd0 + 1][bj] = f2tf32(v0.y);                                      \
        Bs[BUF][bd0 + 2][bj] = f2tf32(v0.z);                                      \
        Bs[BUF][bd0 + 3][bj] = f2tf32(v0.w);                                      \
        Bs[BUF][bd0 + 4][bj] = f2tf32(v1.x);                                      \
        Bs[BUF][bd0 + 5][bj] = f2tf32(v1.y);                                      \
        Bs[BUF][bd0 + 6][bj] = f2tf32(v1.z);                                      \
        Bs[BUF][bd0 + 7][bj] = f2tf32(v1.w);                                      \
    }                                                                             \
} while (0)

    LOAD_TILE(0, 0);
    __syncthreads();

    // per-lane i constants: i_local = mi*32 + mb*16 + h*8 + rr
    float e2v[2][2], p2v[2][2], p52v[2][2];
#pragma unroll
    for (int mb = 0; mb < 2; mb++)
#pragma unroll
        for (int h = 0; h < 2; h++) {
            int il = mi * 32 + mb * 16 + h * 8 + rr;
            e2v[mb][h] = e2t[il];  p2v[mb][h] = p2t[il];  p52v[mb][h] = p52t[il];
        }

    float acc[2][4][4];
#pragma unroll
    for (int mb = 0; mb < 2; mb++)
#pragma unroll
        for (int nb = 0; nb < 4; nb++)
#pragma unroll
            for (int q = 0; q < 4; q++) acc[mb][nb][q] = 0.f;

    for (int jt = 0; jt < NN / 32; jt++) {
        const int bf = jt & 1;
        if (jt + 1 < NN / 32) LOAD_TILE(jt + 1, bf ^ 1);

#pragma unroll
        for (int kb = 0; kb < 4; kb++) {
            const int jb = kb * 8;
            float4 jv1 = jtab[bf][jb + cc];
            float4 jv2 = jtab[bf][jb + cc + 4];
            unsigned mw1 = maskt[bf][(jb + cc) * 4 + mi];
            unsigned mw2 = maskt[bf][(jb + cc + 4) * 4 + mi];

            unsigned afrag[2][4];
#pragma unroll
            for (int mb = 0; mb < 2; mb++)
#pragma unroll
                for (int h = 0; h < 2; h++) {
                    int bp = mb * 16 + h * 8 + rr;
                    float s1 = jv1.x + e2v[mb][h];
                    float w1 = ((mw1 >> bp) & 1u)
                             ? (s1 >= 0.f ? jv1.y * p2v[mb][h] : jv1.z * p52v[mb][h]) : 0.f;
                    float s2 = jv2.x + e2v[mb][h];
                    float w2 = ((mw2 >> bp) & 1u)
                             ? (s2 >= 0.f ? jv2.y * p2v[mb][h] : jv2.z * p52v[mb][h]) : 0.f;
                    afrag[mb][h]     = f2tf32(w1);
                    afrag[mb][2 + h] = f2tf32(w2);
                }
#pragma unroll
            for (int nb = 0; nb < 4; nb++) {
                int n = nh * 32 + nb * 8 + rr;
                unsigned bfr[2];
                bfr[0] = Bs[bf][n][jb + cc];
                bfr[1] = Bs[bf][n][jb + cc + 4];
                mma_tf32(acc[0][nb], afrag[0], bfr);
                mma_tf32(acc[1][nb], afrag[1], bfr);
            }
        }
        __syncthreads();   // compute(bf) done; load(bf^1) done
    }

    // epilogue: bias + relu, float2 stores
    const float* bb = bias + kh * 64;
#pragma unroll
    for (int mb = 0; mb < 2; mb++) {
#pragma unroll
        for (int nb = 0; nb < 4; nb++) {
            int col = nh * 32 + nb * 8 + 2 * cc;
            float2 bv = *(const float2*)(bb + col);
            int iA = i0 + mi * 32 + mb * 16 + rr;
            float2 o0, o1;
            o0.x = fmaxf(acc[mb][nb][0] + bv.x, 0.f);
            o0.y = fmaxf(acc[mb][nb][1] + bv.y, 0.f);
            o1.x = fmaxf(acc[mb][nb][2] + bv.x, 0.f);
            o1.y = fmaxf(acc[mb][nb][3] + bv.y, 0.f);
            *(float2*)(out + (size_t)iA * (KH * DD) + kh * 64 + col) = o0;
            *(float2*)(out + (size_t)(iA + 8) * (KH * DD) + kh * 64 + col) = o1;
        }
    }
#undef LOAD_TILE
}

// ---------------------------------------------------------------------------
extern "C" void kernel_launch(void* const* d_in, const int* in_sizes, int n_in,
                              void* d_out, int out_size) {
    const float* H  = (const float*)d_in[0];   // [8192,256]
    const int*   A  = (const int*)  d_in[1];   // [8192,8192]
    const float* W  = (const float*)d_in[2];   // [2,256,64]
    const float* b  = (const float*)d_in[3];   // [2,64]
    const float* a1 = (const float*)d_in[4];   // [2,64]
    const float* a2 = (const float*)d_in[5];   // [2,64]
    float* out = (float*)d_out;                // [8192,128]

    k_hw <<<NN / 32, 256>>>(H, W);
    k_e  <<<(KH * NN) / 256, 256>>>(a1, a2);
    k_z  <<<NN / 8, 256>>>(A);
    k_out_mma<<<dim3(NN / 128, KH), 256>>>(b, out);
}

// round 6
// speedup vs baseline: 1.2269x; 1.2269x over previous
#include <cuda_runtime.h>
#include <math.h>
#include <cstdint>

#define NN 8192
#define FF 256
#define DD 64
#define KH 2

// ---------------- scratch (static device globals; no allocation) -------------
__device__ float g_HW [KH*NN*DD];     // [k][n][d]
__device__ float g_e1 [KH*NN];
__device__ float g_p1 [KH*NN];        // exp(e1)
__device__ float g_p51[KH*NN];        // exp(0.2 e1)
__device__ float4 g_ip [KH*NN];       // {e2, p2=exp(e2), p52=exp(0.2 e2), 0}
__device__ float4 g_jp [KH*NN];       // {e1, q1=p1/Z, q5=p51/Z, 0}
__device__ unsigned g_mask[NN*(NN/32)];  // bitpacked A, row-major [j][i/32]

// ---------------- small PTX helpers (plain sm_80+ PTX) ----------------------
__device__ __forceinline__ unsigned f2tf32(float f) {
    unsigned r;
    asm("cvt.rna.tf32.f32 %0, %1;" : "=r"(r) : "f"(f));
    return r;
}
__device__ __forceinline__ void mma_tf32(float* d, const unsigned* a, const unsigned* bf) {
    asm volatile(
        "mma.sync.aligned.m16n8k8.row.col.f32.tf32.tf32.f32 "
        "{%0,%1,%2,%3}, {%4,%5,%6,%7}, {%8,%9}, {%0,%1,%2,%3};"
        : "+f"(d[0]), "+f"(d[1]), "+f"(d[2]), "+f"(d[3])
        : "r"(a[0]), "r"(a[1]), "r"(a[2]), "r"(a[3]), "r"(bf[0]), "r"(bf[1]));
}

// ---------------- kernel 1: HW[k][n][d] = sum_f H[n][f] W[k][f][d] ----------
__global__ void k_hw(const float* __restrict__ H, const float* __restrict__ W) {
    __shared__ float Ws[64][128];
    __shared__ float Hs[32][64];
    const int tid = threadIdx.x;
    const int tx = tid & 31;
    const int ty = tid >> 5;
    const int n0 = blockIdx.x * 32;

    float acc[4][4];
#pragma unroll
    for (int a = 0; a < 4; a++)
#pragma unroll
        for (int b = 0; b < 4; b++) acc[a][b] = 0.f;

    for (int fc = 0; fc < FF; fc += 64) {
#pragma unroll
        for (int q = 0; q < 8; q++) {
            int idx = q * 256 + tid;
            int kk = idx >> 5, c4 = idx & 31;
            int c = c4 * 4;
            int k = c >> 6, d = c & 63;
            float4 v = *(const float4*)(W + k * (FF * DD) + (fc + kk) * DD + d);
            *(float4*)(&Ws[kk][c]) = v;
        }
#pragma unroll
        for (int q = 0; q < 2; q++) {
            int idx = q * 256 + tid;
            int r = idx >> 4, k4 = idx & 15;
            float4 v = *(const float4*)(H + (n0 + r) * FF + fc + k4 * 4);
            *(float4*)(&Hs[r][k4 * 4]) = v;
        }
        __syncthreads();
#pragma unroll 8
        for (int kk = 0; kk < 64; kk++) {
            float4 bv = *(const float4*)(&Ws[kk][tx * 4]);
            float a0 = Hs[ty * 4 + 0][kk];
            float a1 = Hs[ty * 4 + 1][kk];
            float a2 = Hs[ty * 4 + 2][kk];
            float a3 = Hs[ty * 4 + 3][kk];
            acc[0][0] += a0 * bv.x; acc[0][1] += a0 * bv.y; acc[0][2] += a0 * bv.z; acc[0][3] += a0 * bv.w;
            acc[1][0] += a1 * bv.x; acc[1][1] += a1 * bv.y; acc[1][2] += a1 * bv.z; acc[1][3] += a1 * bv.w;
            acc[2][0] += a2 * bv.x; acc[2][1] += a2 * bv.y; acc[2][2] += a2 * bv.z; acc[2][3] += a2 * bv.w;
            acc[3][0] += a3 * bv.x; acc[3][1] += a3 * bv.y; acc[3][2] += a3 * bv.z; acc[3][3] += a3 * bv.w;
        }
        __syncthreads();
    }
    const int c = tx * 4;
    const int k = c >> 6, d = c & 63;
#pragma unroll
    for (int s = 0; s < 4; s++) {
        int n = n0 + ty * 4 + s;
        float4 o = make_float4(acc[s][0], acc[s][1], acc[s][2], acc[s][3]);
        *(float4*)(g_HW + (k * NN + n) * DD + d) = o;
    }
}

// ------- kernel 2: e1/e2 per (k,n) + exp tables (packed) --------------------
__global__ void k_e(const float* __restrict__ a1, const float* __restrict__ a2) {
    __shared__ float a1s[128], a2s[128];
    const int tid = threadIdx.x;
    if (tid < 128) a1s[tid] = a1[tid];
    else           a2s[tid - 128] = a2[tid - 128];
    __syncthreads();
    const int t = blockIdx.x * 256 + tid;     // t = k*8192 + n
    const int k = t >> 13;
    const float* hw = g_HW + (size_t)t * DD;
    const float* A1 = a1s + k * 64;
    const float* A2 = a2s + k * 64;
    float e1 = 0.f, e2 = 0.f;
#pragma unroll
    for (int d4 = 0; d4 < 16; d4++) {
        float4 h = *(const float4*)(hw + d4 * 4);
        e1 += h.x * A1[d4 * 4 + 0] + h.y * A1[d4 * 4 + 1] + h.z * A1[d4 * 4 + 2] + h.w * A1[d4 * 4 + 3];
        e2 += h.x * A2[d4 * 4 + 0] + h.y * A2[d4 * 4 + 1] + h.z * A2[d4 * 4 + 2] + h.w * A2[d4 * 4 + 3];
    }
    g_e1[t]  = e1;
    g_p1[t]  = expf(e1);
    g_p51[t] = expf(0.2f * e1);
    g_ip[t]  = make_float4(e2, expf(e2), expf(0.2f * e2), 0.f);
}

// ------- kernel 3: softmax denominators Z + bitpack A -----------------------
// CTA = 8 rows (j), 256 threads, column-per-thread; no smem/syncs in sweep.
__global__ void k_z(const int* __restrict__ A) {
    __shared__ float red[32][8];
    const int tid = threadIdx.x;
    const int lane = tid & 31, wrp = tid >> 5;
    const int j0 = blockIdx.x * 8;

    float e1r[8][2];
#pragma unroll
    for (int j = 0; j < 8; j++) {
        e1r[j][0] = g_e1[j0 + j];
        e1r[j][1] = g_e1[NN + j0 + j];
    }
    float sums[8][2][2];
#pragma unroll
    for (int j = 0; j < 8; j++)
#pragma unroll
        for (int k = 0; k < 2; k++) { sums[j][k][0] = 0.f; sums[j][k][1] = 0.f; }

    for (int ci = 0; ci < 32; ci++) {
        const int col = ci * 256 + tid;
        const float4 ip0 = g_ip[col];
        const float4 ip1 = g_ip[NN + col];
#pragma unroll
        for (int j = 0; j < 8; j++) {
            int a = A[(size_t)(j0 + j) * NN + col];
            unsigned bal = __ballot_sync(0xffffffffu, a != 0);
            if (lane == 0) g_mask[(j0 + j) * (NN / 32) + ci * 8 + wrp] = bal;
            if (a != 0) {
                float s0 = e1r[j][0] + ip0.x;
                if (s0 >= 0.f) sums[j][0][0] += ip0.y; else sums[j][0][1] += ip0.z;
                float s1 = e1r[j][1] + ip1.x;
                if (s1 >= 0.f) sums[j][1][0] += ip1.y; else sums[j][1][1] += ip1.z;
            }
        }
    }
#pragma unroll
    for (int v = 0; v < 32; v++) {
        int j = v >> 2, k = (v >> 1) & 1, tp = v & 1;
        float val = sums[j][k][tp];
        val += __shfl_down_sync(0xffffffffu, val, 16);
        val += __shfl_down_sync(0xffffffffu, val, 8);
        val += __shfl_down_sync(0xffffffffu, val, 4);
        val += __shfl_down_sync(0xffffffffu, val, 2);
        val += __shfl_down_sync(0xffffffffu, val, 1);
        if (lane == 0) red[v][wrp] = val;
    }
    __syncthreads();
    if (tid < 16) {
        int j = tid >> 1, k = tid & 1;
        float s0 = 0.f, s5 = 0.f;
#pragma unroll
        for (int w = 0; w < 8; w++) {
            s0 += red[(j * 2 + k) * 2 + 0][w];
            s5 += red[(j * 2 + k) * 2 + 1][w];
        }
        int gi = k * NN + j0 + j;
        float p1 = g_p1[gi], p51 = g_p51[gi];
        float rZ = 1.0f / (p1 * s0 + p51 * s5);
        g_jp[gi] = make_float4(g_e1[gi], p1 * rZ, p51 * rZ, 0.f);
    }
}

// ------- kernel 4 (mma.sync tf32, pipelined): -------------------------------
// out[k,i,:] = sum_j attn[k,j,i]*HW[k,j,:].  CTA: 128 thr / 4 warps, tile
// M=64 (i) x N=64 (d). Warp w owns m16 rows (mi=w), all 64 d (acc[8][4]).
// Per 32-j tile: prefetch (LDG->regs), compute from smem, convert+STS, sync.
__global__ void __launch_bounds__(128) k_out_mma(const float* __restrict__ bias,
                                                 float* __restrict__ out) {
    __shared__ unsigned Bs[2][64][36];      // tf32 bits, [d][j], stride 36
    __shared__ float4   jtab[2][32];        // {e1, q1, q5, -}
    __shared__ unsigned maskt[2][32][2];    // [j][word]

    const int tid  = threadIdx.x;
    const int wid  = tid >> 5;
    const int lane = tid & 31;
    const int kh   = blockIdx.y;
    const int i0   = blockIdx.x * 64;
    const int kbase = kh * NN;
    const int mrow0 = i0 >> 5;

    const int mi = wid;                 // m16 block 0..3
    const int rr = lane >> 2;           // 0..7
    const int cc = lane & 3;            // 0..3
    const int wsel = mi >> 1;           // mask word within tile
    const int bplo = (mi & 1) * 16 + rr;

    // per-lane i constants from packed table
    const float4 iplo = g_ip[kbase + i0 + mi * 16 + rr];
    const float4 iphi = g_ip[kbase + i0 + mi * 16 + rr + 8];

    // B-stage coords: each thread loads 16 d for one j
    const int bj = tid & 31;
    const int d0 = (tid >> 5) * 16;
    const float4* bsrc_base = (const float4*)(g_HW + (kbase + bj) * DD + d0);

    // mask/jtab prefetch coords (FIX: j index is (tid-32)>>1, word is tid&1)
    const int mjj = (tid - 32) >> 1;    // valid for tid in [32,96): 0..31
    const int mword = tid & 1;

    float4 rB[4];
    float4 rJ;
    unsigned rM = 0;

#define LDG_TILE(JT) do {                                                        \
    const int j0_ = (JT) * 32;                                                   \
    const float4* s_ = bsrc_base + j0_ * (DD / 4);                               \
    rB[0] = s_[0]; rB[1] = s_[1]; rB[2] = s_[2]; rB[3] = s_[3];                  \
    if (tid < 32)      rJ = g_jp[kbase + j0_ + tid];                             \
    else if (tid < 96) rM = g_mask[(j0_ + mjj) * (NN / 32) + mrow0 + mword];     \
} while (0)

#define STS_TILE(BUF) do {                                                       \
    float vv[16];                                                                \
    *(float4*)(vv + 0)  = rB[0]; *(float4*)(vv + 4)  = rB[1];                    \
    *(float4*)(vv + 8)  = rB[2]; *(float4*)(vv + 12) = rB[3];                    \
    _Pragma("unroll")                                                            \
    for (int s = 0; s < 16; s++) Bs[BUF][d0 + s][bj] = f2tf32(vv[s]);            \
    if (tid < 32)      jtab[BUF][tid] = rJ;                                      \
    else if (tid < 96) maskt[BUF][mjj][mword] = rM;                              \
} while (0)

    float acc[8][4];
#pragma unroll
    for (int nb = 0; nb < 8; nb++)
#pragma unroll
        for (int q = 0; q < 4; q++) acc[nb][q] = 0.f;

    LDG_TILE(0);
    STS_TILE(0);
    __syncthreads();

    for (int jt = 0; jt < NN / 32; jt++) {
        const int bf = jt & 1;
        if (jt + 1 < NN / 32) LDG_TILE(jt + 1);

#pragma unroll
        for (int kb = 0; kb < 4; kb++) {
            const int jb = kb * 8;
            const float4 jv1 = jtab[bf][jb + cc];
            const float4 jv2 = jtab[bf][jb + cc + 4];
            const unsigned t1 = maskt[bf][jb + cc][wsel] >> bplo;
            const unsigned t2 = maskt[bf][jb + cc + 4][wsel] >> bplo;

            unsigned afr[4];
            float s;
            s = jv1.x + iplo.x;
            afr[0] = f2tf32((t1 & 1u)   ? (s >= 0.f ? jv1.y * iplo.y : jv1.z * iplo.z) : 0.f);
            s = jv1.x + iphi.x;
            afr[1] = f2tf32((t1 & 256u) ? (s >= 0.f ? jv1.y * iphi.y : jv1.z * iphi.z) : 0.f);
            s = jv2.x + iplo.x;
            afr[2] = f2tf32((t2 & 1u)   ? (s >= 0.f ? jv2.y * iplo.y : jv2.z * iplo.z) : 0.f);
            s = jv2.x + iphi.x;
            afr[3] = f2tf32((t2 & 256u) ? (s >= 0.f ? jv2.y * iphi.y : jv2.z * iphi.z) : 0.f);

#pragma unroll
            for (int nb = 0; nb < 8; nb++) {
                unsigned bfr[2];
                bfr[0] = Bs[bf][nb * 8 + rr][jb + cc];
                bfr[1] = Bs[bf][nb * 8 + rr][jb + cc + 4];
                mma_tf32(acc[nb], afr, bfr);
            }
        }

        if (jt + 1 < NN / 32) STS_TILE(bf ^ 1);
        __syncthreads();
    }

    // epilogue: bias + relu, float2 stores
    const float* bb = bias + kh * 64;
    const int ilo = i0 + mi * 16 + rr;
#pragma unroll
    for (int nb = 0; nb < 8; nb++) {
        int col = nb * 8 + 2 * cc;
        float2 bv = *(const float2*)(bb + col);
        float2 o0, o1;
        o0.x = fmaxf(acc[nb][0] + bv.x, 0.f);
        o0.y = fmaxf(acc[nb][1] + bv.y, 0.f);
        o1.x = fmaxf(acc[nb][2] + bv.x, 0.f);
        o1.y = fmaxf(acc[nb][3] + bv.y, 0.f);
        *(float2*)(out + (size_t)ilo * (KH * DD) + kh * 64 + col) = o0;
        *(float2*)(out + (size_t)(ilo + 8) * (KH * DD) + kh * 64 + col) = o1;
    }
#undef LDG_TILE
#undef STS_TILE
}

// ---------------------------------------------------------------------------
extern "C" void kernel_launch(void* const* d_in, const int* in_sizes, int n_in,
                              void* d_out, int out_size) {
    const float* H  = (const float*)d_in[0];   // [8192,256]
    const int*   A  = (const int*)  d_in[1];   // [8192,8192]
    const float* W  = (const float*)d_in[2];   // [2,256,64]
    const float* b  = (const float*)d_in[3];   // [2,64]
    const float* a1 = (const float*)d_in[4];   // [2,64]
    const float* a2 = (const float*)d_in[5];   // [2,64]
    float* out = (float*)d_out;                // [8192,128]

    k_hw <<<NN / 32, 256>>>(H, W);
    k_e  <<<(KH * NN) / 256, 256>>>(a1, a2);
    k_z  <<<NN / 8, 256>>>(A);
    k_out_mma<<<dim3(NN / 64, KH), 128>>>(b, out);
}

// round 7
// speedup vs baseline: 1.5166x; 1.2361x over previous
#include <cuda_runtime.h>
#include <math.h>
#include <cstdint>

#define NN 8192
#define FF 256
#define DD 64
#define KH 2
#define JSPLIT 4

// ---------------- scratch (static device globals; no allocation) -------------
__device__ float g_HW [KH*NN*DD];     // [k][n][d]
__device__ float g_e1 [KH*NN];
__device__ float g_p1 [KH*NN];        // exp(e1)
__device__ float g_p51[KH*NN];        // exp(0.2 e1)
__device__ float4 g_ip [KH*NN];       // {e2, p2=exp(e2), p52=exp(0.2 e2), 0}
__device__ float4 g_jp [KH*NN];       // {e1, q1=p1/Z, q5=p51/Z, 0}
__device__ unsigned g_mask[NN*(NN/32)];  // bitpacked A, row-major [j][i/32]
__device__ float g_part[JSPLIT*KH*NN*DD]; // partial outputs [s][k][i][d]

// ---------------- small PTX helpers (plain sm_80+ PTX) ----------------------
__device__ __forceinline__ unsigned f2tf32(float f) {
    unsigned r;
    asm("cvt.rna.tf32.f32 %0, %1;" : "=r"(r) : "f"(f));
    return r;
}
__device__ __forceinline__ void mma_tf32(float* d, const unsigned* a, const unsigned* bf) {
    asm volatile(
        "mma.sync.aligned.m16n8k8.row.col.f32.tf32.tf32.f32 "
        "{%0,%1,%2,%3}, {%4,%5,%6,%7}, {%8,%9}, {%0,%1,%2,%3};"
        : "+f"(d[0]), "+f"(d[1]), "+f"(d[2]), "+f"(d[3])
        : "r"(a[0]), "r"(a[1]), "r"(a[2]), "r"(a[3]), "r"(bf[0]), "r"(bf[1]));
}

// ---------------- kernel 1: HW[k][n][d] = sum_f H[n][f] W[k][f][d] ----------
__global__ void k_hw(const float* __restrict__ H, const float* __restrict__ W) {
    __shared__ float Ws[64][128];
    __shared__ float Hs[32][64];
    const int tid = threadIdx.x;
    const int tx = tid & 31;
    const int ty = tid >> 5;
    const int n0 = blockIdx.x * 32;

    float acc[4][4];
#pragma unroll
    for (int a = 0; a < 4; a++)
#pragma unroll
        for (int b = 0; b < 4; b++) acc[a][b] = 0.f;

    for (int fc = 0; fc < FF; fc += 64) {
#pragma unroll
        for (int q = 0; q < 8; q++) {
            int idx = q * 256 + tid;
            int kk = idx >> 5, c4 = idx & 31;
            int c = c4 * 4;
            int k = c >> 6, d = c & 63;
            float4 v = *(const float4*)(W + k * (FF * DD) + (fc + kk) * DD + d);
            *(float4*)(&Ws[kk][c]) = v;
        }
#pragma unroll
        for (int q = 0; q < 2; q++) {
            int idx = q * 256 + tid;
            int r = idx >> 4, k4 = idx & 15;
            float4 v = *(const float4*)(H + (n0 + r) * FF + fc + k4 * 4);
            *(float4*)(&Hs[r][k4 * 4]) = v;
        }
        __syncthreads();
#pragma unroll 8
        for (int kk = 0; kk < 64; kk++) {
            float4 bv = *(const float4*)(&Ws[kk][tx * 4]);
            float a0 = Hs[ty * 4 + 0][kk];
            float a1 = Hs[ty * 4 + 1][kk];
            float a2 = Hs[ty * 4 + 2][kk];
            float a3 = Hs[ty * 4 + 3][kk];
            acc[0][0] += a0 * bv.x; acc[0][1] += a0 * bv.y; acc[0][2] += a0 * bv.z; acc[0][3] += a0 * bv.w;
            acc[1][0] += a1 * bv.x; acc[1][1] += a1 * bv.y; acc[1][2] += a1 * bv.z; acc[1][3] += a1 * bv.w;
            acc[2][0] += a2 * bv.x; acc[2][1] += a2 * bv.y; acc[2][2] += a2 * bv.z; acc[2][3] += a2 * bv.w;
            acc[3][0] += a3 * bv.x; acc[3][1] += a3 * bv.y; acc[3][2] += a3 * bv.z; acc[3][3] += a3 * bv.w;
        }
        __syncthreads();
    }
    const int c = tx * 4;
    const int k = c >> 6, d = c & 63;
#pragma unroll
    for (int s = 0; s < 4; s++) {
        int n = n0 + ty * 4 + s;
        float4 o = make_float4(acc[s][0], acc[s][1], acc[s][2], acc[s][3]);
        *(float4*)(g_HW + (k * NN + n) * DD + d) = o;
    }
}

// ------- kernel 2: e1/e2 per (k,n) + exp tables (packed) --------------------
__global__ void k_e(const float* __restrict__ a1, const float* __restrict__ a2) {
    __shared__ float a1s[128], a2s[128];
    const int tid = threadIdx.x;
    if (tid < 128) a1s[tid] = a1[tid];
    else           a2s[tid - 128] = a2[tid - 128];
    __syncthreads();
    const int t = blockIdx.x * 256 + tid;     // t = k*8192 + n
    const int k = t >> 13;
    const float* hw = g_HW + (size_t)t * DD;
    const float* A1 = a1s + k * 64;
    const float* A2 = a2s + k * 64;
    float e1 = 0.f, e2 = 0.f;
#pragma unroll
    for (int d4 = 0; d4 < 16; d4++) {
        float4 h = *(const float4*)(hw + d4 * 4);
        e1 += h.x * A1[d4 * 4 + 0] + h.y * A1[d4 * 4 + 1] + h.z * A1[d4 * 4 + 2] + h.w * A1[d4 * 4 + 3];
        e2 += h.x * A2[d4 * 4 + 0] + h.y * A2[d4 * 4 + 1] + h.z * A2[d4 * 4 + 2] + h.w * A2[d4 * 4 + 3];
    }
    g_e1[t]  = e1;
    g_p1[t]  = expf(e1);
    g_p51[t] = expf(0.2f * e1);
    g_ip[t]  = make_float4(e2, expf(e2), expf(0.2f * e2), 0.f);
}

// ------- kernel 3: softmax denominators Z + bitpack A -----------------------
__global__ void k_z(const int* __restrict__ A) {
    __shared__ float red[32][8];
    const int tid = threadIdx.x;
    const int lane = tid & 31, wrp = tid >> 5;
    const int j0 = blockIdx.x * 8;

    float e1r[8][2];
#pragma unroll
    for (int j = 0; j < 8; j++) {
        e1r[j][0] = g_e1[j0 + j];
        e1r[j][1] = g_e1[NN + j0 + j];
    }
    float sums[8][2][2];
#pragma unroll
    for (int j = 0; j < 8; j++)
#pragma unroll
        for (int k = 0; k < 2; k++) { sums[j][k][0] = 0.f; sums[j][k][1] = 0.f; }

    for (int ci = 0; ci < 32; ci++) {
        const int col = ci * 256 + tid;
        const float4 ip0 = g_ip[col];
        const float4 ip1 = g_ip[NN + col];
#pragma unroll
        for (int j = 0; j < 8; j++) {
            int a = A[(size_t)(j0 + j) * NN + col];
            unsigned bal = __ballot_sync(0xffffffffu, a != 0);
            if (lane == 0) g_mask[(j0 + j) * (NN / 32) + ci * 8 + wrp] = bal;
            if (a != 0) {
                float s0 = e1r[j][0] + ip0.x;
                if (s0 >= 0.f) sums[j][0][0] += ip0.y; else sums[j][0][1] += ip0.z;
                float s1 = e1r[j][1] + ip1.x;
                if (s1 >= 0.f) sums[j][1][0] += ip1.y; else sums[j][1][1] += ip1.z;
            }
        }
    }
#pragma unroll
    for (int v = 0; v < 32; v++) {
        int j = v >> 2, k = (v >> 1) & 1, tp = v & 1;
        float val = sums[j][k][tp];
        val += __shfl_down_sync(0xffffffffu, val, 16);
        val += __shfl_down_sync(0xffffffffu, val, 8);
        val += __shfl_down_sync(0xffffffffu, val, 4);
        val += __shfl_down_sync(0xffffffffu, val, 2);
        val += __shfl_down_sync(0xffffffffu, val, 1);
        if (lane == 0) red[v][wrp] = val;
    }
    __syncthreads();
    if (tid < 16) {
        int j = tid >> 1, k = tid & 1;
        float s0 = 0.f, s5 = 0.f;
#pragma unroll
        for (int w = 0; w < 8; w++) {
            s0 += red[(j * 2 + k) * 2 + 0][w];
            s5 += red[(j * 2 + k) * 2 + 1][w];
        }
        int gi = k * NN + j0 + j;
        float p1 = g_p1[gi], p51 = g_p51[gi];
        float rZ = 1.0f / (p1 * s0 + p51 * s5);
        g_jp[gi] = make_float4(g_e1[gi], p1 * rZ, p51 * rZ, 0.f);
    }
}

// ------- kernel 4 (mma.sync tf32, pipelined, j-split): ----------------------
// CTA (bx, kh, s): i-tile bx*64, head kh, j-range [s*2048, s*2048+2048).
// Partial sums go to g_part[s][kh][i][d]; k_fin reduces.
__global__ void __launch_bounds__(128) k_out_mma(float* __restrict__ part) {
    __shared__ unsigned Bs[2][64][36];      // tf32 bits, [d][j], stride 36
    __shared__ float4   jtab[2][32];        // {e1, q1, q5, -}
    __shared__ unsigned maskt[2][32][2];    // [j][word]

    const int tid  = threadIdx.x;
    const int wid  = tid >> 5;
    const int lane = tid & 31;
    const int kh   = blockIdx.y;
    const int spl  = blockIdx.z;
    const int i0   = blockIdx.x * 64;
    const int kbase = kh * NN;
    const int mrow0 = i0 >> 5;
    const int jt0  = spl * (NN / 32 / JSPLIT);     // 64 tiles per split
    const int jt1  = jt0 + (NN / 32 / JSPLIT);

    const int mi = wid;                 // m16 block 0..3
    const int rr = lane >> 2;           // 0..7
    const int cc = lane & 3;            // 0..3
    const int wsel = mi >> 1;           // mask word within tile
    const int bplo = (mi & 1) * 16 + rr;

    const float4 iplo = g_ip[kbase + i0 + mi * 16 + rr];
    const float4 iphi = g_ip[kbase + i0 + mi * 16 + rr + 8];

    const int bj = tid & 31;
    const int d0 = (tid >> 5) * 16;
    const float4* bsrc_base = (const float4*)(g_HW + (kbase + bj) * DD + d0);

    const int mjj = (tid - 32) >> 1;    // valid for tid in [32,96): 0..31
    const int mword = tid & 1;

    float4 rB[4];
    float4 rJ;
    unsigned rM = 0;

#define LDG_TILE(JT) do {                                                        \
    const int j0_ = (JT) * 32;                                                   \
    const float4* s_ = bsrc_base + j0_ * (DD / 4);                               \
    rB[0] = s_[0]; rB[1] = s_[1]; rB[2] = s_[2]; rB[3] = s_[3];                  \
    if (tid < 32)      rJ = g_jp[kbase + j0_ + tid];                             \
    else if (tid < 96) rM = g_mask[(j0_ + mjj) * (NN / 32) + mrow0 + mword];     \
} while (0)

#define STS_TILE(BUF) do {                                                       \
    float vv[16];                                                                \
    *(float4*)(vv + 0)  = rB[0]; *(float4*)(vv + 4)  = rB[1];                    \
    *(float4*)(vv + 8)  = rB[2]; *(float4*)(vv + 12) = rB[3];                    \
    _Pragma("unroll")                                                            \
    for (int s = 0; s < 16; s++) Bs[BUF][d0 + s][bj] = f2tf32(vv[s]);            \
    if (tid < 32)      jtab[BUF][tid] = rJ;                                      \
    else if (tid < 96) maskt[BUF][mjj][mword] = rM;                              \
} while (0)

    float acc[8][4];
#pragma unroll
    for (int nb = 0; nb < 8; nb++)
#pragma unroll
        for (int q = 0; q < 4; q++) acc[nb][q] = 0.f;

    LDG_TILE(jt0);
    STS_TILE(0);
    __syncthreads();

    for (int jt = jt0; jt < jt1; jt++) {
        const int bf = (jt - jt0) & 1;
        if (jt + 1 < jt1) LDG_TILE(jt + 1);

#pragma unroll
        for (int kb = 0; kb < 4; kb++) {
            const int jb = kb * 8;
            const float4 jv1 = jtab[bf][jb + cc];
            const float4 jv2 = jtab[bf][jb + cc + 4];
            const unsigned t1 = maskt[bf][jb + cc][wsel] >> bplo;
            const unsigned t2 = maskt[bf][jb + cc + 4][wsel] >> bplo;

            unsigned afr[4];
            float s;
            s = jv1.x + iplo.x;
            afr[0] = f2tf32((t1 & 1u)   ? (s >= 0.f ? jv1.y * iplo.y : jv1.z * iplo.z) : 0.f);
            s = jv1.x + iphi.x;
            afr[1] = f2tf32((t1 & 256u) ? (s >= 0.f ? jv1.y * iphi.y : jv1.z * iphi.z) : 0.f);
            s = jv2.x + iplo.x;
            afr[2] = f2tf32((t2 & 1u)   ? (s >= 0.f ? jv2.y * iplo.y : jv2.z * iplo.z) : 0.f);
            s = jv2.x + iphi.x;
            afr[3] = f2tf32((t2 & 256u) ? (s >= 0.f ? jv2.y * iphi.y : jv2.z * iphi.z) : 0.f);

#pragma unroll
            for (int nb = 0; nb < 8; nb++) {
                unsigned bfr[2];
                bfr[0] = Bs[bf][nb * 8 + rr][jb + cc];
                bfr[1] = Bs[bf][nb * 8 + rr][jb + cc + 4];
                mma_tf32(acc[nb], afr, bfr);
            }
        }

        if (jt + 1 < jt1) STS_TILE(bf ^ 1);
        __syncthreads();
    }

    // epilogue: write raw partials to g_part[spl][kh][i][d]
    float* pbase = part + ((size_t)(spl * KH + kh) * NN) * DD;
    const int ilo = i0 + mi * 16 + rr;
#pragma unroll
    for (int nb = 0; nb < 8; nb++) {
        int col = nb * 8 + 2 * cc;
        *(float2*)(pbase + (size_t)ilo * DD + col) = make_float2(acc[nb][0], acc[nb][1]);
        *(float2*)(pbase + (size_t)(ilo + 8) * DD + col) = make_float2(acc[nb][2], acc[nb][3]);
    }
#undef LDG_TILE
#undef STS_TILE
}

// ------- kernel 5: reduce partials + bias + relu ----------------------------
__global__ void k_fin(const float* __restrict__ bias, float* __restrict__ out) {
    const int t = blockIdx.x * 256 + threadIdx.x;   // float4 id over [NN][K*D]
    const int d4 = t & 31;            // 0..31 (float4 within 128-float row)
    const int i  = t >> 5;
    const int kh = d4 >> 4;           // head
    const int dd4 = d4 & 15;          // float4 within head (d = dd4*4)
    const size_t pidx = (((size_t)kh * NN + i) * DD + dd4 * 4) / 4;

    const float4* P = (const float4*)g_part;
    const size_t stride4 = (size_t)KH * NN * DD / 4;
    float4 s0 = P[pidx];
    float4 s1 = P[pidx + stride4];
    float4 s2 = P[pidx + 2 * stride4];
    float4 s3 = P[pidx + 3 * stride4];
    float4 bv = *(const float4*)(bias + kh * DD + dd4 * 4);
    float4 o;
    o.x = fmaxf((s0.x + s1.x) + (s2.x + s3.x) + bv.x, 0.f);
    o.y = fmaxf((s0.y + s1.y) + (s2.y + s3.y) + bv.y, 0.f);
    o.z = fmaxf((s0.z + s1.z) + (s2.z + s3.z) + bv.z, 0.f);
    o.w = fmaxf((s0.w + s1.w) + (s2.w + s3.w) + bv.w, 0.f);
    ((float4*)out)[t] = o;
}

// ---------------------------------------------------------------------------
extern "C" void kernel_launch(void* const* d_in, const int* in_sizes, int n_in,
                              void* d_out, int out_size) {
    const float* H  = (const float*)d_in[0];   // [8192,256]
    const int*   A  = (const int*)  d_in[1];   // [8192,8192]
    const float* W  = (const float*)d_in[2];   // [2,256,64]
    const float* b  = (const float*)d_in[3];   // [2,64]
    const float* a1 = (const float*)d_in[4];   // [2,64]
    const float* a2 = (const float*)d_in[5];   // [2,64]
    float* out = (float*)d_out;                // [8192,128]

    float* part;
    cudaGetSymbolAddress((void**)&part, g_part);

    k_hw <<<NN / 32, 256>>>(H, W);
    k_e  <<<(KH * NN) / 256, 256>>>(a1, a2);
    k_z  <<<NN / 8, 256>>>(A);
    k_out_mma<<<dim3(NN / 64, KH, JSPLIT), 128>>>(part);
    k_fin<<<(NN * KH * DD / 4) / 256, 256>>>(b, out);
}